// round 17
// baseline (speedup 1.0000x reference)
#include <cuda_runtime.h>
#include <cuda_fp16.h>

#define BATCH   256
#define FEAT    4096
#define FMASK   (FEAT - 1)
#define NSUB    8            // sub-bins per row
#define SUBCAP  48           // capacity per sub-bin (Poisson(18.3), ~7-sigma margin)
#define ROWCAP  (NSUB * SUBCAP)  // 384 slots per row
#define TR_BLOCKS 512        // transpose CTAs (2 tiles each) inside merged prep

// ---- scratch (device globals; no allocation allowed) ----
__device__ __half g_xTh[FEAT * BATCH];      // x transposed, fp16: (FEAT, BATCH), 2 MB
__device__ int    g_cnt[FEAT * NSUB];       // 8 sub-counters per row (memset node)
__device__ int2   g_bin[FEAT * ROWCAP];     // packed {col, val(fp32)} sub-bins, 12.6 MB

// ---- 1. merged prep: transpose (2 tiles/CTA, MLP=2)  ||  scatter into sub-bins ----
__global__ void __launch_bounds__(256) prep(const float* __restrict__ x,
                                            const int* __restrict__ st,
                                            const float* __restrict__ stv,
                                            const int* __restrict__ sn,
                                            const float* __restrict__ snv,
                                            int nnzT, int nnzN) {
    if (blockIdx.x < TR_BLOCKS) {
        // ---- transpose path: two adjacent 32x32 feature tiles per CTA ----
        __shared__ float tile[2][32][33];
        int f0 = (blockIdx.x & 63) * 64;         // 64 features per CTA
        int b0 = (blockIdx.x >> 6) * 32;
        int i = threadIdx.x;
        {
            int row = i >> 3;            // batch row 0..31
            int q   = i & 7;             // feature quad 0..7
            // two independent loads in flight (MLP=2)
            float4 va = *(const float4*)&x[(b0 + row) * FEAT + f0 + q * 4];
            float4 vb = *(const float4*)&x[(b0 + row) * FEAT + f0 + 32 + q * 4];
            tile[0][row][q * 4 + 0] = va.x;
            tile[0][row][q * 4 + 1] = va.y;
            tile[0][row][q * 4 + 2] = va.z;
            tile[0][row][q * 4 + 3] = va.w;
            tile[1][row][q * 4 + 0] = vb.x;
            tile[1][row][q * 4 + 1] = vb.y;
            tile[1][row][q * 4 + 2] = vb.z;
            tile[1][row][q * 4 + 3] = vb.w;
        }
        __syncthreads();
        {
            int f  = i >> 3;             // feature 0..31
            int bq = i & 7;              // batch quad 0..7
            __half2 lo0 = __floats2half2_rn(tile[0][bq * 4 + 0][f], tile[0][bq * 4 + 1][f]);
            __half2 hi0 = __floats2half2_rn(tile[0][bq * 4 + 2][f], tile[0][bq * 4 + 3][f]);
            __half2 lo1 = __floats2half2_rn(tile[1][bq * 4 + 0][f], tile[1][bq * 4 + 1][f]);
            __half2 hi1 = __floats2half2_rn(tile[1][bq * 4 + 2][f], tile[1][bq * 4 + 3][f]);
            uint2 p0, p1;
            p0.x = *(unsigned*)&lo0; p0.y = *(unsigned*)&hi0;
            p1.x = *(unsigned*)&lo1; p1.y = *(unsigned*)&hi1;
            *(uint2*)&g_xTh[(f0 + f) * BATCH + b0 + bq * 4]      = p0;
            *(uint2*)&g_xTh[(f0 + 32 + f) * BATCH + b0 + bq * 4] = p1;
        }
    } else {
        // ---- scatter path: one nnz per thread, 8-way split row counters ----
        int i = (blockIdx.x - TR_BLOCKS) * 256 + threadIdx.x;
        if (i >= nnzT + nnzN) return;
        int r, c; float v;
        if (i < nnzT) {
            r = st[i];
            c = st[nnzT + i];
            v = stv[i];
        } else {
            int j = i - nnzT;
            r = sn[j];
            c = sn[nnzN + j];
            v = snv[j];
        }
        r &= FMASK;
        int sub = i & (NSUB - 1);        // contention per counter: ~18
        int pos = atomicAdd(&g_cnt[r * NSUB + sub], 1);
        if (pos < SUBCAP)                // overflow statistically impossible; guarded
            g_bin[r * ROWCAP + sub * SUBCAP + pos] = make_int2(c & FMASK, __float_as_int(v));
    }
}

// packed f32x2 fma: acc += xf2 * vv   (sm_103a FFMA2)
__device__ __forceinline__ void fma2p(unsigned long long& acc, float2 xf, unsigned long long vv) {
    unsigned long long xp;
    asm("mov.b64 %0, {%1, %2};" : "=l"(xp) : "f"(xf.x), "f"(xf.y));
    asm("fma.rn.f32x2 %0, %1, %2, %0;" : "+l"(acc) : "l"(xp), "l"(vv));
}

// ---- 2. main SpMM: CTA = one row, 4 warps; warp w walks sub-bins w and w+4
//         (~37 nnz total, same balance as r16). smem combine, direct output. ----
__global__ void __launch_bounds__(128) spmm_main(const float* __restrict__ bias,
                                                 float* __restrict__ out) {
    __shared__ float part[4][BATCH];     // 4 KB
    int w    = threadIdx.x >> 5;         // warp 0..3
    int lane = threadIdx.x & 31;
    int r = blockIdx.x;

    const uint4* xh = (const uint4*)g_xTh;              // row stride = 32 uint4

    unsigned long long a0 = 0, a1 = 0, a2 = 0, a3 = 0;  // 8 fp32 accum as 4x f32x2

#define ACCQ(q, vbits)                                                   \
    {                                                                    \
        float v = __int_as_float(vbits);                                 \
        unsigned long long vv;                                           \
        asm("mov.b64 %0, {%1, %2};" : "=l"(vv) : "f"(v), "f"(v));        \
        fma2p(a0, __half22float2(*(__half2*)&q.x), vv);                  \
        fma2p(a1, __half22float2(*(__half2*)&q.y), vv);                  \
        fma2p(a2, __half22float2(*(__half2*)&q.z), vv);                  \
        fma2p(a3, __half22float2(*(__half2*)&q.w), vv);                  \
    }

#pragma unroll
    for (int half = 0; half < 2; half++) {
        int sub = w + half * 4;
        int n = __ldg(&g_cnt[r * NSUB + sub]);
        if (n > SUBCAP) n = SUBCAP;
        const int2* bin = g_bin + r * ROWCAP + sub * SUBCAP;
        const int4* bp  = (const int4*)bin;             // sub-bin base 16B-aligned

        int j = 0;
        for (; j + 8 <= n; j += 8) {
            int4 b0 = __ldg(&bp[(j >> 1) + 0]);
            int4 b1 = __ldg(&bp[(j >> 1) + 1]);
            int4 b2 = __ldg(&bp[(j >> 1) + 2]);
            int4 b3 = __ldg(&bp[(j >> 1) + 3]);
            uint4 x0 = __ldg(&xh[b0.x * 32 + lane]);
            uint4 x1 = __ldg(&xh[b0.z * 32 + lane]);
            uint4 x2 = __ldg(&xh[b1.x * 32 + lane]);
            uint4 x3 = __ldg(&xh[b1.z * 32 + lane]);
            uint4 x4 = __ldg(&xh[b2.x * 32 + lane]);
            uint4 x5 = __ldg(&xh[b2.z * 32 + lane]);
            uint4 x6 = __ldg(&xh[b3.x * 32 + lane]);
            uint4 x7 = __ldg(&xh[b3.z * 32 + lane]);
            ACCQ(x0, b0.y) ACCQ(x1, b0.w)
            ACCQ(x2, b1.y) ACCQ(x3, b1.w)
            ACCQ(x4, b2.y) ACCQ(x5, b2.w)
            ACCQ(x6, b3.y) ACCQ(x7, b3.w)
        }
        for (; j < n; j++) {
            int2 p = __ldg(&bin[j]);
            uint4 xq = __ldg(&xh[p.x * 32 + lane]);
            ACCQ(xq, p.y)
        }
    }
#undef ACCQ

    // unpack -> 8 floats, park in smem
    float o0, o1, o2, o3, o4, o5, o6, o7;
    asm("mov.b64 {%0, %1}, %2;" : "=f"(o0), "=f"(o1) : "l"(a0));
    asm("mov.b64 {%0, %1}, %2;" : "=f"(o2), "=f"(o3) : "l"(a1));
    asm("mov.b64 {%0, %1}, %2;" : "=f"(o4), "=f"(o5) : "l"(a2));
    asm("mov.b64 {%0, %1}, %2;" : "=f"(o6), "=f"(o7) : "l"(a3));
    int b = lane * 8;
    *(float4*)&part[w][b]     = make_float4(o0, o1, o2, o3);
    *(float4*)&part[w][b + 4] = make_float4(o4, o5, o6, o7);
    __syncthreads();

    // combine: thread t sums 2 batches over the 4 warp-partials, adds bias, stores
    float bv = __ldg(&bias[r]);
    int bb = threadIdx.x * 2;
#pragma unroll
    for (int k = 0; k < 2; k++) {
        int bi = bb + k;
        float s = part[0][bi] + part[1][bi] + part[2][bi] + part[3][bi];
        out[bi * FEAT + r] = s + bv;
    }
}

extern "C" void kernel_launch(void* const* d_in, const int* in_sizes, int n_in,
                              void* d_out, int out_size) {
    const float* x       = (const float*)d_in[0];
    const int*   st_idx  = (const int*)d_in[1];
    const float* st_vals = (const float*)d_in[2];
    const int*   sn_idx  = (const int*)d_in[3];
    const float* sn_vals = (const float*)d_in[4];
    const float* bias    = (const float*)d_in[5];

    int nnzT  = in_sizes[2];
    int nnzN  = in_sizes[4];
    int total = nnzT + nnzN;

    // zero sub-counters with one memset node (graph-capturable, not an alloc)
    void* cnt_ptr = nullptr;
    cudaGetSymbolAddress(&cnt_ptr, g_cnt);
    cudaMemsetAsync(cnt_ptr, 0, FEAT * NSUB * sizeof(int));

    int scatter_blocks = (total + 255) / 256;
    prep<<<TR_BLOCKS + scatter_blocks, 256>>>(x, st_idx, st_vals, sn_idx, sn_vals, nnzT, nnzN);
    // CTA per row, 4 warps x 2 sub-bins each, ~2 waves
    spmm_main<<<FEAT, 128>>>(bias, (float*)d_out);
}